// round 5
// baseline (speedup 1.0000x reference)
#include <cuda_runtime.h>

// Izhikevich neuron simulation on GB300 — round 4: warp-specialized pipeline.
// input:  [32, 2000, 512] fp32; output: concat(s, v, u), each [32, 2000, 512].
//
// 512 CTAs x 160 threads (5 warps). Each CTA owns 32 consecutive sequences.
//   warp 0: compute  — serial Izhikevich chain, SMEM in -> SMEM out
//   warp 1: producer — GMEM input -> SMEM, prefetched one chunk ahead (regs)
//   warp 2/3/4: store spikes / voltages / recovery, SMEM -> GMEM
// Double-buffered chunks of 20 steps, one __syncthreads per chunk.

#define BATCH    32
#define NSTEPS   2000
#define NNEUR    512
#define PLANE    (NSTEPS * NNEUR)
#define NTOT     (BATCH * PLANE)
#define CHUNK    20
#define NCHUNKS  (NSTEPS / CHUNK)        // 100
#define CHEL     (CHUNK * NNEUR)         // gmem elements per chunk stride

__global__ __launch_bounds__(160, 4)
void izhikevich_kernel(const float* __restrict__ in,
                       float* __restrict__ out_s,
                       float* __restrict__ out_v,
                       float* __restrict__ out_u)
{
    __shared__ float s_in[2][CHUNK][32];
    __shared__ float s_s [2][CHUNK][32];
    __shared__ float s_v [2][CHUNK][32];
    __shared__ float s_u [2][CHUNK][32];

    const int wid  = threadIdx.x >> 5;
    const int lane = threadIdx.x & 31;
    const int seq  = blockIdx.x * 32 + lane;     // this lane's sequence
    const int b    = seq >> 9;
    const int n    = seq & 511;
    const int base = b * PLANE + n;              // < 2^25, fits int

    const float* __restrict__ ip = in + base;

    // compute-warp state
    float v = -65.0f;
    float u = -13.0f;        // B * C
    // producer prefetch registers
    float r[CHUNK];

    // ---- prologue: producer fills buffer 0 and preloads chunk 1 ----
    if (wid == 1) {
        #pragma unroll
        for (int j = 0; j < CHUNK; ++j) r[j] = __ldcs(ip + j * NNEUR);
        #pragma unroll
        for (int j = 0; j < CHUNK; ++j) s_in[0][j][lane] = r[j];
        #pragma unroll
        for (int j = 0; j < CHUNK; ++j) r[j] = __ldcs(ip + (CHUNK + j) * NNEUR);
    }
    __syncthreads();

    #pragma unroll 1
    for (int k = 0; k < NCHUNKS; ++k) {
        const int p = k & 1;

        if (wid == 0) {
            // ---- compute chunk k: serial chain only, SMEM <-> SMEM ----
            #pragma unroll
            for (int j = 0; j < CHUNK; ++j) {
                float i_t = s_in[p][j][lane];
                // exact reference association order — do not reassociate
                float dv = (0.04f * v * v + 5.0f * v + 140.0f - u + i_t) * 0.5f;
                float du = (0.02f * (0.2f * v - u)) * 0.5f;
                v = v + dv;
                u = u + du;
                bool  fired = (v >= 30.0f);
                float s = fired ? 1.0f : 0.0f;
                v = fired ? -65.0f : v;
                u = fired ? u + 8.0f : u;
                s_s[p][j][lane] = s;
                s_v[p][j][lane] = v;
                s_u[p][j][lane] = u;
            }
        } else if (wid == 1) {
            // ---- producer: publish chunk k+1, prefetch chunk k+2 ----
            if (k + 1 < NCHUNKS) {
                const int p1 = (k + 1) & 1;
                #pragma unroll
                for (int j = 0; j < CHUNK; ++j) s_in[p1][j][lane] = r[j];
                if (k + 2 < NCHUNKS) {
                    const float* q = ip + (k + 2) * CHEL;
                    #pragma unroll
                    for (int j = 0; j < CHUNK; ++j) r[j] = __ldcs(q + j * NNEUR);
                }
            }
        } else if (k >= 1) {
            // ---- store warps: drain chunk k-1 of their stream ----
            const int pm  = (k - 1) & 1;
            const int off = base + (k - 1) * CHEL;
            const float (*buf)[32] =
                (wid == 2) ? s_s[pm] : (wid == 3) ? s_v[pm] : s_u[pm];
            float* __restrict__ g =
                ((wid == 2) ? out_s : (wid == 3) ? out_v : out_u) + off;
            #pragma unroll
            for (int j = 0; j < CHUNK; ++j)
                __stcs(g + j * NNEUR, buf[j][lane]);
        }

        __syncthreads();
    }

    // ---- epilogue: drain the final chunk (parity (NCHUNKS-1)&1 = 1) ----
    if (wid >= 2) {
        const int pm  = (NCHUNKS - 1) & 1;
        const int off = base + (NCHUNKS - 1) * CHEL;
        const float (*buf)[32] =
            (wid == 2) ? s_s[pm] : (wid == 3) ? s_v[pm] : s_u[pm];
        float* __restrict__ g =
            ((wid == 2) ? out_s : (wid == 3) ? out_v : out_u) + off;
        #pragma unroll
        for (int j = 0; j < CHUNK; ++j)
            __stcs(g + j * NNEUR, buf[j][lane]);
    }
}

extern "C" void kernel_launch(void* const* d_in, const int* in_sizes, int n_in,
                              void* d_out, int out_size)
{
    const float* in = (const float*)d_in[0];
    float* out      = (float*)d_out;

    izhikevich_kernel<<<512, 160>>>(in, out, out + NTOT, out + 2 * NTOT);
}